// round 4
// baseline (speedup 1.0000x reference)
#include <cuda_runtime.h>

// Problem constants (fixed: P=64, K=8, C=512, N=1536)
#define NROWS 1536
#define CDIM  512
#define MCL   192
#define GK    8
#define MARGIN_KL 6.0f
#define MID_N 1024
#define MID_M 128
#define NBLOCKS 148     // == #SMs on B200: persistent, all co-resident
#define NTILES  144     // 48 x 3 tiles of 32x64
#define NEPI    96      // epilogue blocks (16 rows each)

// Static device scratch
__device__ float g_xs[NROWS * CDIM];
__device__ float g_rowc[NROWS];          // ent_x + lse
__device__ float g_hcT[CDIM * MCL];      // hcen^T k-major
__device__ float g_lhT[CDIM * MCL];      // logh^T k-major
__device__ float g_enth[MCL];
__device__ float g_pd[2 * NROWS * MCL];  // K-half partial products
__device__ float g_part[NEPI * 4];
__device__ unsigned int g_ctr  = 0;
__device__ unsigned int g_bcnt = 0;
__device__ unsigned int g_bgen = 0;

// ---------------- packed f32x2 helpers ----------------
__device__ __forceinline__ void fma2(unsigned long long& d,
                                     unsigned long long a, unsigned long long b) {
    asm("fma.rn.f32x2 %0, %1, %2, %0;" : "+l"(d) : "l"(a), "l"(b));
}
__device__ __forceinline__ void upk2(unsigned long long v, float& lo, float& hi) {
    asm("mov.b64 {%0, %1}, %2;" : "=f"(lo), "=f"(hi) : "l"(v));
}

// ---------------- grid-wide barrier (all NBLOCKS co-resident) --------------
__device__ __forceinline__ void grid_sync() {
    __syncthreads();
    if (threadIdx.x == 0) {
        const unsigned int gen = ((volatile unsigned int*)&g_bgen)[0];
        __threadfence();
        if (atomicAdd(&g_bcnt, 1u) == NBLOCKS - 1) {
            g_bcnt = 0;
            __threadfence();
            atomicExch(&g_bgen, gen + 1u);
        } else {
            while (((volatile unsigned int*)&g_bgen)[0] == gen) __nanosleep(64);
        }
        __threadfence();
    }
    __syncthreads();
}

// GEMM smem per half-block unit (20992 B); 2 units = 41984 B
struct SmemB {
    float sax[16][36];    // x tile, k-major (pad 36)
    float sas[16][36];    // xs tile
    float sbh[16][128];   // hcen tile, duplicated pairs
    float sbl[16][128];   // logh tile, duplicated pairs
};

__global__ void __launch_bounds__(256, 1) k_all(const float* __restrict__ x,
                                                const long long* __restrict__ pids,
                                                float* __restrict__ out) {
    __shared__ __align__(16) char smem_raw[41984];
    __shared__ float sred[8];
    __shared__ float rp[8], rn[8];
    __shared__ int cp[8], cn[8];
    __shared__ bool slast;

    const int b = blockIdx.x;
    const int t = threadIdx.x;
    const int w = t >> 5, lane = t & 31;

    // ======================= Phase A: softmax stats + centers ==============
    {
        float (*sxs)[516] = (float(*)[516])smem_raw;
        #pragma unroll
        for (int ci = 0; ci < 2; ci++) {
            const int j = b + NBLOCKS * ci;
            if (j < MCL) {                      // block-uniform predicate
                const int row = j * GK + w;     // warp w handles row w of cluster
                const float4* xr = reinterpret_cast<const float4*>(x + (size_t)row * CDIM);
                float4 v[4];
                #pragma unroll
                for (int q = 0; q < 4; q++) v[q] = xr[lane + 32 * q];

                float mx = -1e30f;
                #pragma unroll
                for (int q = 0; q < 4; q++)
                    mx = fmaxf(mx, fmaxf(fmaxf(v[q].x, v[q].y), fmaxf(v[q].z, v[q].w)));
                #pragma unroll
                for (int o = 16; o; o >>= 1) mx = fmaxf(mx, __shfl_xor_sync(0xffffffffu, mx, o));

                float4 e[4]; float s = 0.f;
                #pragma unroll
                for (int q = 0; q < 4; q++) {
                    e[q].x = __expf(v[q].x - mx); e[q].y = __expf(v[q].y - mx);
                    e[q].z = __expf(v[q].z - mx); e[q].w = __expf(v[q].w - mx);
                    s += (e[q].x + e[q].y) + (e[q].z + e[q].w);
                }
                #pragma unroll
                for (int o = 16; o; o >>= 1) s += __shfl_xor_sync(0xffffffffu, s, o);

                const float lse = mx + logf(s);
                const float inv = 1.0f / s;
                float4* gx = reinterpret_cast<float4*>(g_xs + (size_t)row * CDIM);
                float4* sx = reinterpret_cast<float4*>(&sxs[w][0]);
                float ent = 0.f;
                #pragma unroll
                for (int q = 0; q < 4; q++) {
                    float4 p = make_float4(e[q].x * inv, e[q].y * inv, e[q].z * inv, e[q].w * inv);
                    gx[lane + 32 * q] = p;
                    sx[lane + 32 * q] = p;
                    ent += p.x * (v[q].x - lse) + p.y * (v[q].y - lse)
                         + p.z * (v[q].z - lse) + p.w * (v[q].w - lse);
                }
                #pragma unroll
                for (int o = 16; o; o >>= 1) ent += __shfl_xor_sync(0xffffffffu, ent, o);
                if (lane == 0) g_rowc[row] = ent + lse;

                __syncthreads();

                // centers: thread t -> columns t, t+256
                float entp = 0.f;
                #pragma unroll
                for (int hh = 0; hh < 2; hh++) {
                    const int c = t + 256 * hh;
                    float hc = 0.f;
                    #pragma unroll
                    for (int r = 0; r < GK; r++) hc += sxs[r][c];
                    hc *= (1.0f / (float)GK);
                    const float l = logf(fmaxf(hc, 1e-9f));
                    g_hcT[c * MCL + j] = hc;
                    g_lhT[c * MCL + j] = l;
                    entp += hc * l;
                }
                #pragma unroll
                for (int o = 16; o; o >>= 1) entp += __shfl_xor_sync(0xffffffffu, entp, o);
                if (lane == 0) sred[w] = entp;
                __syncthreads();
                if (t == 0) {
                    float eh = 0.f;
                    #pragma unroll
                    for (int r = 0; r < 8; r++) eh += sred[r];
                    g_enth[j] = eh;
                }
                __syncthreads();   // protect sxs reuse by next cluster
            }
        }
    }

    grid_sync();

    // ======================= Phase B: dual-GEMM, split-K halves ============
    if (b < NTILES) {
        const int h = t >> 7;          // half 0/1 = K-half
        const int wg_t = t & 127;
        const int bi = b % 48;
        const int bj = b / 48;
        const int khb = h * 256;       // K-half base
        SmemB* sm = reinterpret_cast<SmemB*>(smem_raw) + h;

        const int ti = wg_t >> 4;      // 0..7 : rows ti*4..+3
        const int tj = wg_t & 15;      // 0..15: cols tj*4..+3
        const int arow = wg_t >> 2;    // 0..31
        const int acol = (wg_t & 3) * 4;
        const int bkk0 = wg_t >> 4;            // B loader: kk = bkk0 + 8*s ... (see below)
        const int bjf  = (wg_t & 15) * 4;

        unsigned long long acc[2][4];
        #pragma unroll
        for (int c = 0; c < 4; c++) { acc[0][c] = 0ull; acc[1][c] = 0ull; }

        float4 pax, pas, pbh[2], pbl[2];
        // prefetch chunk 0
        {
            const size_t ga = (size_t)(bi * 32 + arow) * CDIM + khb + acol;
            pax = *reinterpret_cast<const float4*>(x + ga);
            pas = *reinterpret_cast<const float4*>(g_xs + ga);
            #pragma unroll
            for (int s = 0; s < 2; s++) {
                const int kk = bkk0 + 8 * s;
                const size_t gb = (size_t)(khb + kk) * MCL + bj * 64 + bjf;
                pbh[s] = *reinterpret_cast<const float4*>(g_hcT + gb);
                pbl[s] = *reinterpret_cast<const float4*>(g_lhT + gb);
            }
        }

        for (int ch = 0; ch < 16; ch++) {
            // store A (k-major scalars)
            sm->sax[acol + 0][arow] = pax.x; sm->sax[acol + 1][arow] = pax.y;
            sm->sax[acol + 2][arow] = pax.z; sm->sax[acol + 3][arow] = pax.w;
            sm->sas[acol + 0][arow] = pas.x; sm->sas[acol + 1][arow] = pas.y;
            sm->sas[acol + 2][arow] = pas.z; sm->sas[acol + 3][arow] = pas.w;
            // store B duplicated pairs
            #pragma unroll
            for (int s = 0; s < 2; s++) {
                const int kk = bkk0 + 8 * s;
                float4 bv = pbh[s];
                *reinterpret_cast<float4*>(&sm->sbh[kk][2 * bjf]) =
                    make_float4(bv.x, bv.x, bv.y, bv.y);
                *reinterpret_cast<float4*>(&sm->sbh[kk][2 * bjf + 4]) =
                    make_float4(bv.z, bv.z, bv.w, bv.w);
                bv = pbl[s];
                *reinterpret_cast<float4*>(&sm->sbl[kk][2 * bjf]) =
                    make_float4(bv.x, bv.x, bv.y, bv.y);
                *reinterpret_cast<float4*>(&sm->sbl[kk][2 * bjf + 4]) =
                    make_float4(bv.z, bv.z, bv.w, bv.w);
            }
            asm volatile("bar.sync %0, 128;" :: "r"(h + 1) : "memory");

            if (ch < 15) {
                const int k0 = khb + (ch + 1) * 16;
                const size_t ga = (size_t)(bi * 32 + arow) * CDIM + k0 + acol;
                pax = *reinterpret_cast<const float4*>(x + ga);
                pas = *reinterpret_cast<const float4*>(g_xs + ga);
                #pragma unroll
                for (int s = 0; s < 2; s++) {
                    const int kk = bkk0 + 8 * s;
                    const size_t gb = (size_t)(k0 + kk) * MCL + bj * 64 + bjf;
                    pbh[s] = *reinterpret_cast<const float4*>(g_hcT + gb);
                    pbl[s] = *reinterpret_cast<const float4*>(g_lhT + gb);
                }
            }

            #pragma unroll
            for (int kk = 0; kk < 16; kk++) {
                const ulonglong2 ax = *reinterpret_cast<const ulonglong2*>(&sm->sax[kk][ti * 4]);
                const ulonglong2 as_ = *reinterpret_cast<const ulonglong2*>(&sm->sas[kk][ti * 4]);
                const ulonglong2 bh0 = *reinterpret_cast<const ulonglong2*>(&sm->sbh[kk][tj * 8]);
                const ulonglong2 bh1 = *reinterpret_cast<const ulonglong2*>(&sm->sbh[kk][tj * 8 + 4]);
                const ulonglong2 bl0 = *reinterpret_cast<const ulonglong2*>(&sm->sbl[kk][tj * 8]);
                const ulonglong2 bl1 = *reinterpret_cast<const ulonglong2*>(&sm->sbl[kk][tj * 8 + 4]);
                fma2(acc[0][0], ax.x, bh0.x); fma2(acc[0][1], ax.x, bh0.y);
                fma2(acc[0][2], ax.x, bh1.x); fma2(acc[0][3], ax.x, bh1.y);
                fma2(acc[1][0], ax.y, bh0.x); fma2(acc[1][1], ax.y, bh0.y);
                fma2(acc[1][2], ax.y, bh1.x); fma2(acc[1][3], ax.y, bh1.y);
                fma2(acc[0][0], as_.x, bl0.x); fma2(acc[0][1], as_.x, bl0.y);
                fma2(acc[0][2], as_.x, bl1.x); fma2(acc[0][3], as_.x, bl1.y);
                fma2(acc[1][0], as_.y, bl0.x); fma2(acc[1][1], as_.y, bl0.y);
                fma2(acc[1][2], as_.y, bl1.x); fma2(acc[1][3], as_.y, bl1.y);
            }
            asm volatile("bar.sync %0, 128;" :: "r"(h + 1) : "memory");
        }

        // write 4x4 partial tile to this K-half plane
        float* outp = g_pd + (size_t)h * (NROWS * MCL);
        const int ibase = bi * 32 + ti * 4;
        const int jbase = bj * 64 + tj * 4;
        float4 r0, r1, r2, r3;
        upk2(acc[0][0], r0.x, r1.x); upk2(acc[0][1], r0.y, r1.y);
        upk2(acc[0][2], r0.z, r1.z); upk2(acc[0][3], r0.w, r1.w);
        upk2(acc[1][0], r2.x, r3.x); upk2(acc[1][1], r2.y, r3.y);
        upk2(acc[1][2], r2.z, r3.z); upk2(acc[1][3], r2.w, r3.w);
        *reinterpret_cast<float4*>(outp + (size_t)(ibase + 0) * MCL + jbase) = r0;
        *reinterpret_cast<float4*>(outp + (size_t)(ibase + 1) * MCL + jbase) = r1;
        *reinterpret_cast<float4*>(outp + (size_t)(ibase + 2) * MCL + jbase) = r2;
        *reinterpret_cast<float4*>(outp + (size_t)(ibase + 3) * MCL + jbase) = r3;
    }

    grid_sync();

    // ======================= Phase C: epilogue + final reduce ==============
    if (b < NEPI) {
        float* senth = (float*)smem_raw;                   // [192]
        float* srowc = senth + 192;                        // [16]
        long long* sph = (long long*)(srowc + 16);         // [192]
        long long* spid = sph + 192;                       // [16]

        const int ibase = b * 16;
        if (t < MCL) {
            senth[t] = g_enth[t];
            sph[t] = pids[(size_t)t * GK];
        }
        if (t >= 192 && t < 208) {
            const int r = t - 192;
            srowc[r] = g_rowc[ibase + r];
            spid[r] = pids[ibase + r];
        }
        __syncthreads();

        float psum = 0.f, nsum = 0.f;
        int pcnt = 0, ncnt = 0;
        #pragma unroll
        for (int q = 0; q < 3; q++) {
            const int idx = t + 256 * q;         // 0..767
            const int r = idx / 48;
            const int jf = (idx % 48) * 4;
            const int i = ibase + r;
            const float4 p0 = *reinterpret_cast<const float4*>(g_pd + (size_t)i * MCL + jf);
            const float4 p1 = *reinterpret_cast<const float4*>(
                g_pd + (size_t)(NROWS * MCL) + (size_t)i * MCL + jf);
            const float rc = srowc[r];
            const long long pi = spid[r];
            const bool itop = i < MID_N;
            const float dv[4] = { rc + senth[jf + 0] - p0.x - p1.x,
                                  rc + senth[jf + 1] - p0.y - p1.y,
                                  rc + senth[jf + 2] - p0.z - p1.z,
                                  rc + senth[jf + 3] - p0.w - p1.w };
            #pragma unroll
            for (int c = 0; c < 4; c++) {
                const bool mask = (pi == sph[jf + c]);
                const bool region = itop != ((jf + c) < MID_M);
                if (mask) {
                    if (region) { psum += dv[c]; pcnt++; }
                } else {
                    nsum += fmaxf(MARGIN_KL - dv[c], 0.f);
                    ncnt++;
                }
            }
        }

        #pragma unroll
        for (int o = 16; o; o >>= 1) {
            psum += __shfl_xor_sync(0xffffffffu, psum, o);
            nsum += __shfl_xor_sync(0xffffffffu, nsum, o);
            pcnt += __shfl_xor_sync(0xffffffffu, pcnt, o);
            ncnt += __shfl_xor_sync(0xffffffffu, ncnt, o);
        }
        if (lane == 0) { rp[w] = psum; rn[w] = nsum; cp[w] = pcnt; cn[w] = ncnt; }
        __syncthreads();
        if (t == 0) {
            float fp = 0.f, fn = 0.f; int ip = 0, in_ = 0;
            #pragma unroll
            for (int q = 0; q < 8; q++) { fp += rp[q]; fn += rn[q]; ip += cp[q]; in_ += cn[q]; }
            g_part[b * 4 + 0] = fp;
            g_part[b * 4 + 1] = fn;
            g_part[b * 4 + 2] = (float)ip;
            g_part[b * 4 + 3] = (float)in_;
            __threadfence();
            slast = (atomicAdd(&g_ctr, 1u) == NEPI - 1);
        }
        __syncthreads();

        if (slast) {
            __threadfence();
            float ps = 0.f, ns = 0.f, pc = 0.f, nc = 0.f;
            if (t < NEPI) {
                ps = g_part[t * 4 + 0];
                ns = g_part[t * 4 + 1];
                pc = g_part[t * 4 + 2];
                nc = g_part[t * 4 + 3];
            }
            #pragma unroll
            for (int o = 16; o; o >>= 1) {
                ps += __shfl_xor_sync(0xffffffffu, ps, o);
                ns += __shfl_xor_sync(0xffffffffu, ns, o);
                pc += __shfl_xor_sync(0xffffffffu, pc, o);
                nc += __shfl_xor_sync(0xffffffffu, nc, o);
            }
            if (lane == 0) { rp[w] = ps; rn[w] = ns; cp[w] = (int)pc; cn[w] = (int)nc; }
            __syncthreads();
            if (t == 0) {
                float fps = 0.f, fns = 0.f, fpc = 0.f, fnc = 0.f;
                #pragma unroll
                for (int q = 0; q < 8; q++) {
                    fps += rp[q]; fns += rn[q];
                    fpc += (float)cp[q]; fnc += (float)cn[q];
                }
                out[0] = fps / fmaxf(fpc, 1.0f) + fns / fmaxf(fnc, 1.0f);
                g_ctr = 0;   // reset for next graph replay
            }
        }
    }
}

// ---------------------------------------------------------------------------
extern "C" void kernel_launch(void* const* d_in, const int* in_sizes, int n_in,
                              void* d_out, int out_size) {
    const float* x = (const float*)d_in[0];
    const long long* pids = (const long long*)d_in[1];
    (void)in_sizes; (void)n_in; (void)out_size;

    k_all<<<NBLOCKS, 256>>>(x, pids, (float*)d_out);
}

// round 5
// speedup vs baseline: 1.8359x; 1.8359x over previous
#include <cuda_runtime.h>

// Problem constants (fixed: P=64, K=8, C=512, N=1536)
#define NROWS 1536
#define CDIM  512
#define MCL   192
#define GK    8
#define MARGIN_KL 6.0f
#define MID_N 1024
#define MID_M 128
#define GBI   48
#define GBJ   3
#define NBLK  (GBI * GBJ * 2)    // 288 gemm blocks (co-resident: <= 148*2)

// Static device scratch
__device__ float g_xs[NROWS * CDIM];
__device__ float g_rowc[NROWS];          // ent_x + lse
__device__ float g_hcT[CDIM * MCL];      // hcen^T k-major
__device__ float g_lhT[CDIM * MCL];      // logh^T k-major
__device__ float g_enth[MCL];
__device__ float g_pd[2 * NROWS * MCL];  // partial products per z-plane
__device__ float g_part[NBLK * 4];
__device__ unsigned int g_ctr  = 0;
__device__ unsigned int g_bcnt = 0;
__device__ unsigned int g_bgen = 0;      // monotonically increasing generation

// ---------------- packed f32x2 helpers ----------------
__device__ __forceinline__ unsigned long long pk2(float lo, float hi) {
    unsigned long long r;
    asm("mov.b64 %0, {%1, %2};" : "=l"(r) : "f"(lo), "f"(hi));
    return r;
}
__device__ __forceinline__ void fma2(unsigned long long& d,
                                     unsigned long long a, unsigned long long b) {
    asm("fma.rn.f32x2 %0, %1, %2, %0;" : "+l"(d) : "l"(a), "l"(b));
}
__device__ __forceinline__ void upk2(unsigned long long v, float& lo, float& hi) {
    asm("mov.b64 {%0, %1}, %2;" : "=f"(lo), "=f"(hi) : "l"(v));
}

// ---------------- grid barrier over NBLK co-resident blocks ----------------
__device__ __forceinline__ void grid_sync_288() {
    __syncthreads();
    if (threadIdx.x == 0) {
        const unsigned int gen = ((volatile unsigned int*)&g_bgen)[0];
        __threadfence();
        if (atomicAdd(&g_bcnt, 1u) == NBLK - 1) {
            g_bcnt = 0;
            __threadfence();
            atomicExch(&g_bgen, gen + 1u);
        } else {
            while (((volatile unsigned int*)&g_bgen)[0] == gen) __nanosleep(32);
        }
        __threadfence();
    }
    __syncthreads();
}

// ---------------------------------------------------------------------------
// Kernel 1: fused softmax stats + centers (fast-math exp/log).
// 192 blocks x 256 threads; warp w handles row 8*j + w.
// ---------------------------------------------------------------------------
__global__ void __launch_bounds__(256) k_stats(const float* __restrict__ x) {
    __shared__ float sxs[8][516];
    __shared__ float sred[8];
    const int j = blockIdx.x;
    const int t = threadIdx.x;
    const int w = t >> 5, lane = t & 31;
    const int row = j * GK + w;

    const float4* xr = reinterpret_cast<const float4*>(x + (size_t)row * CDIM);
    float4 v[4];
    #pragma unroll
    for (int q = 0; q < 4; q++) v[q] = xr[lane + 32 * q];

    float mx = -1e30f;
    #pragma unroll
    for (int q = 0; q < 4; q++)
        mx = fmaxf(mx, fmaxf(fmaxf(v[q].x, v[q].y), fmaxf(v[q].z, v[q].w)));
    #pragma unroll
    for (int o = 16; o; o >>= 1) mx = fmaxf(mx, __shfl_xor_sync(0xffffffffu, mx, o));

    float4 e[4];
    float s = 0.f;
    #pragma unroll
    for (int q = 0; q < 4; q++) {
        e[q].x = __expf(v[q].x - mx); e[q].y = __expf(v[q].y - mx);
        e[q].z = __expf(v[q].z - mx); e[q].w = __expf(v[q].w - mx);
        s += (e[q].x + e[q].y) + (e[q].z + e[q].w);
    }
    #pragma unroll
    for (int o = 16; o; o >>= 1) s += __shfl_xor_sync(0xffffffffu, s, o);

    const float lse = mx + __logf(s);
    const float inv = 1.0f / s;

    float4* gx = reinterpret_cast<float4*>(g_xs + (size_t)row * CDIM);
    float4* sx = reinterpret_cast<float4*>(&sxs[w][0]);
    float ent = 0.f;
    #pragma unroll
    for (int q = 0; q < 4; q++) {
        float4 p = make_float4(e[q].x * inv, e[q].y * inv, e[q].z * inv, e[q].w * inv);
        gx[lane + 32 * q] = p;
        sx[lane + 32 * q] = p;
        ent += p.x * (v[q].x - lse) + p.y * (v[q].y - lse)
             + p.z * (v[q].z - lse) + p.w * (v[q].w - lse);
    }
    #pragma unroll
    for (int o = 16; o; o >>= 1) ent += __shfl_xor_sync(0xffffffffu, ent, o);
    if (lane == 0) g_rowc[row] = ent + lse;

    __syncthreads();

    float entp = 0.f;
    #pragma unroll
    for (int h = 0; h < 2; h++) {
        const int c = t + 256 * h;
        float hc = 0.f;
        #pragma unroll
        for (int r = 0; r < GK; r++) hc += sxs[r][c];
        hc *= (1.0f / (float)GK);
        const float l = __logf(fmaxf(hc, 1e-9f));
        g_hcT[c * MCL + j] = hc;
        g_lhT[c * MCL + j] = l;
        entp += hc * l;
    }
    #pragma unroll
    for (int o = 16; o; o >>= 1) entp += __shfl_xor_sync(0xffffffffu, entp, o);
    if (lane == 0) sred[w] = entp;
    __syncthreads();
    if (t == 0) {
        float eh = 0.f;
        #pragma unroll
        for (int r = 0; r < 8; r++) eh += sred[r];
        g_enth[j] = eh;
    }
}

// ---------------------------------------------------------------------------
// Kernel 2: z-split GEMM (round-3 proven inner loop) + grid barrier +
// distributed epilogue + last-block final reduce.
// Grid (48, 3, 2) = 288 blocks, 128 threads, 2 CTAs/SM (all co-resident).
// ---------------------------------------------------------------------------
__global__ void __launch_bounds__(128, 2) k_gemm_epi(const float* __restrict__ x,
                                                     const long long* __restrict__ pids,
                                                     float* __restrict__ out) {
    __shared__ float sa[32][36];   // [kk][row]
    __shared__ float sb[32][64];   // [kk][j]
    __shared__ float rp[4], rn[4];
    __shared__ int cp[4], cn[4];
    __shared__ bool slast;

    const int bi = blockIdx.x;     // 0..47
    const int bj = blockIdx.y;     // 0..2
    const int z  = blockIdx.z;     // 0..1
    const int t  = threadIdx.x;
    const int ti = t >> 4;         // 0..7
    const int tj = t & 15;         // 0..15

    const float* __restrict__ A = z ? g_xs : x;
    const float* __restrict__ B = z ? g_lhT : g_hcT;
    float* __restrict__ outp = g_pd + (size_t)z * (NROWS * MCL);

    const int arow = t >> 2;
    const int acol = (t & 3) * 4;

    unsigned long long acc[2][4];
    #pragma unroll
    for (int c = 0; c < 4; c++) { acc[0][c] = 0ull; acc[1][c] = 0ull; }

    float4 a0, a1, bst[4];
    {
        const size_t ga = (size_t)(bi * 32 + arow) * CDIM + acol;
        a0 = *reinterpret_cast<const float4*>(A + ga);
        a1 = *reinterpret_cast<const float4*>(A + ga + 16);
        #pragma unroll
        for (int sbk = 0; sbk < 4; sbk++) {
            const int idx = t + 128 * sbk;
            const int kk = idx >> 4, jf = (idx & 15) * 4;
            bst[sbk] = *reinterpret_cast<const float4*>(B + (size_t)kk * MCL + bj * 64 + jf);
        }
    }

    for (int ch = 0; ch < CDIM / 32; ch++) {
        sa[acol + 0][arow] = a0.x; sa[acol + 1][arow] = a0.y;
        sa[acol + 2][arow] = a0.z; sa[acol + 3][arow] = a0.w;
        sa[acol + 16][arow] = a1.x; sa[acol + 17][arow] = a1.y;
        sa[acol + 18][arow] = a1.z; sa[acol + 19][arow] = a1.w;
        #pragma unroll
        for (int sbk = 0; sbk < 4; sbk++) {
            const int idx = t + 128 * sbk;
            const int kk = idx >> 4, jf = (idx & 15) * 4;
            *reinterpret_cast<float4*>(&sb[kk][jf]) = bst[sbk];
        }
        __syncthreads();

        if (ch < CDIM / 32 - 1) {
            const int k0 = (ch + 1) * 32;
            const size_t ga = (size_t)(bi * 32 + arow) * CDIM + k0 + acol;
            a0 = *reinterpret_cast<const float4*>(A + ga);
            a1 = *reinterpret_cast<const float4*>(A + ga + 16);
            #pragma unroll
            for (int sbk = 0; sbk < 4; sbk++) {
                const int idx = t + 128 * sbk;
                const int kk = idx >> 4, jf = (idx & 15) * 4;
                bst[sbk] = *reinterpret_cast<const float4*>(B + (size_t)(k0 + kk) * MCL + bj * 64 + jf);
            }
        }

        #pragma unroll
        for (int kk = 0; kk < 32; kk++) {
            const ulonglong2 aa = *reinterpret_cast<const ulonglong2*>(&sa[kk][ti * 4]);
            const float4 bv = *reinterpret_cast<const float4*>(&sb[kk][tj * 4]);
            const unsigned long long b0 = pk2(bv.x, bv.x);
            const unsigned long long b1 = pk2(bv.y, bv.y);
            const unsigned long long b2 = pk2(bv.z, bv.z);
            const unsigned long long b3 = pk2(bv.w, bv.w);
            fma2(acc[0][0], aa.x, b0);
            fma2(acc[0][1], aa.x, b1);
            fma2(acc[0][2], aa.x, b2);
            fma2(acc[0][3], aa.x, b3);
            fma2(acc[1][0], aa.y, b0);
            fma2(acc[1][1], aa.y, b1);
            fma2(acc[1][2], aa.y, b2);
            fma2(acc[1][3], aa.y, b3);
        }
        __syncthreads();
    }

    // write 4x4 partial tile
    {
        const int ibase = bi * 32 + ti * 4;
        const int jbase = bj * 64 + tj * 4;
        float4 r0, r1, r2, r3;
        upk2(acc[0][0], r0.x, r1.x); upk2(acc[0][1], r0.y, r1.y);
        upk2(acc[0][2], r0.z, r1.z); upk2(acc[0][3], r0.w, r1.w);
        upk2(acc[1][0], r2.x, r3.x); upk2(acc[1][1], r2.y, r3.y);
        upk2(acc[1][2], r2.z, r3.z); upk2(acc[1][3], r2.w, r3.w);
        *reinterpret_cast<float4*>(outp + (size_t)(ibase + 0) * MCL + jbase) = r0;
        *reinterpret_cast<float4*>(outp + (size_t)(ibase + 1) * MCL + jbase) = r1;
        *reinterpret_cast<float4*>(outp + (size_t)(ibase + 2) * MCL + jbase) = r2;
        *reinterpret_cast<float4*>(outp + (size_t)(ibase + 3) * MCL + jbase) = r3;
    }

    // ---- all 288 blocks rendezvous; then share the epilogue ----
    grid_sync_288();

    // smem reuse for epilogue tables (after barrier's __syncthreads)
    float* senth = (float*)&sa[0][0];                 // [192]
    long long* sph = (long long*)&sb[0][0];           // [192]
    for (int c = t; c < MCL; c += 128) {
        senth[c] = g_enth[c];
        sph[c] = pids[(size_t)c * GK];
    }
    __syncthreads();

    const int blk = (bi * GBJ + bj) * 2 + z;          // 0..287
    const int gbase = blk * 256;                      // float4-group base (73728 total)

    float psum = 0.f, nsum = 0.f;
    int pcnt = 0, ncnt = 0;
    #pragma unroll
    for (int q = 0; q < 2; q++) {
        const int g = gbase + t + 128 * q;            // group id
        const int i = g / 48;
        const int jf = (g % 48) * 4;
        const float4 p0 = *reinterpret_cast<const float4*>(g_pd + (size_t)i * MCL + jf);
        const float4 p1 = *reinterpret_cast<const float4*>(
            g_pd + (size_t)(NROWS * MCL) + (size_t)i * MCL + jf);
        const float rc = g_rowc[i];
        const long long pi = pids[i];
        const bool itop = i < MID_N;
        const float dv[4] = { rc + senth[jf + 0] - p0.x - p1.x,
                              rc + senth[jf + 1] - p0.y - p1.y,
                              rc + senth[jf + 2] - p0.z - p1.z,
                              rc + senth[jf + 3] - p0.w - p1.w };
        #pragma unroll
        for (int c = 0; c < 4; c++) {
            const bool mask = (pi == sph[jf + c]);
            const bool region = itop != ((jf + c) < MID_M);
            if (mask) {
                if (region) { psum += dv[c]; pcnt++; }
            } else {
                nsum += fmaxf(MARGIN_KL - dv[c], 0.f);
                ncnt++;
            }
        }
    }

    #pragma unroll
    for (int o = 16; o; o >>= 1) {
        psum += __shfl_xor_sync(0xffffffffu, psum, o);
        nsum += __shfl_xor_sync(0xffffffffu, nsum, o);
        pcnt += __shfl_xor_sync(0xffffffffu, pcnt, o);
        ncnt += __shfl_xor_sync(0xffffffffu, ncnt, o);
    }
    const int w = t >> 5;
    if ((t & 31) == 0) { rp[w] = psum; rn[w] = nsum; cp[w] = pcnt; cn[w] = ncnt; }
    __syncthreads();
    if (t == 0) {
        g_part[blk * 4 + 0] = (rp[0] + rp[1]) + (rp[2] + rp[3]);
        g_part[blk * 4 + 1] = (rn[0] + rn[1]) + (rn[2] + rn[3]);
        g_part[blk * 4 + 2] = (float)((cp[0] + cp[1]) + (cp[2] + cp[3]));
        g_part[blk * 4 + 3] = (float)((cn[0] + cn[1]) + (cn[2] + cn[3]));
        __threadfence();
        slast = (atomicAdd(&g_ctr, 1u) == NBLK - 1);
    }
    __syncthreads();

    if (slast) {
        __threadfence();
        float ps = 0.f, ns = 0.f, pc = 0.f, nc = 0.f;
        for (int b2 = t; b2 < NBLK; b2 += 128) {
            ps += g_part[b2 * 4 + 0];
            ns += g_part[b2 * 4 + 1];
            pc += g_part[b2 * 4 + 2];
            nc += g_part[b2 * 4 + 3];
        }
        #pragma unroll
        for (int o = 16; o; o >>= 1) {
            ps += __shfl_xor_sync(0xffffffffu, ps, o);
            ns += __shfl_xor_sync(0xffffffffu, ns, o);
            pc += __shfl_xor_sync(0xffffffffu, pc, o);
            nc += __shfl_xor_sync(0xffffffffu, nc, o);
        }
        if ((t & 31) == 0) { rp[w] = ps; rn[w] = ns; cp[w] = (int)pc; cn[w] = (int)nc; }
        __syncthreads();
        if (t == 0) {
            const float fps = (rp[0] + rp[1]) + (rp[2] + rp[3]);
            const float fns = (rn[0] + rn[1]) + (rn[2] + rn[3]);
            const float fpc = (float)((cp[0] + cp[1]) + (cp[2] + cp[3]));
            const float fnc = (float)((cn[0] + cn[1]) + (cn[2] + cn[3]));
            out[0] = fps / fmaxf(fpc, 1.0f) + fns / fmaxf(fnc, 1.0f);
            g_ctr = 0;   // reset for next graph replay
        }
    }
}

// ---------------------------------------------------------------------------
extern "C" void kernel_launch(void* const* d_in, const int* in_sizes, int n_in,
                              void* d_out, int out_size) {
    const float* x = (const float*)d_in[0];
    const long long* pids = (const long long*)d_in[1];
    (void)in_sizes; (void)n_in; (void)out_size;

    k_stats<<<MCL, 256>>>(x);
    dim3 gg(GBI, GBJ, 2);
    k_gemm_epi<<<gg, 128>>>(x, pids, (float*)d_out);
}